// round 10
// baseline (speedup 1.0000x reference)
#include <cuda_runtime.h>
#include <cuda_fp16.h>
#include <math.h>
#include <stdint.h>

#define BB 2
#define SS 1024
#define TT (BB*SS)          // 2048 tokens
#define DD 2048
#define HH 16
#define GG 4
#define DKK 128
#define DVV 128
#define NE 8
#define KTOP 2
#define FF 4096
#define MAXROWS (TT*KTOP + NE*128)   // 5120
#define MAXTILES (MAXROWS/128)       // 40

// ---------------- scratch (device globals; no allocs allowed) ----------------
__device__ __half g_hh[TT*DD];              // rms1 out (fp16)
__device__ __half g_qh[TT*HH*DKK];          // post-rope fp16 (written by qkv epilogue)
__device__ __half g_kh[TT*GG*DKK];
__device__ __half g_vh[TT*GG*DVV];
__device__ __half g_attnh[TT*HH*DVV];       // attention out (fp16)
__device__ float  g_x1[TT*DD];              // residual after attn (fp32)
__device__ float  g_t[TT*DD];               // rms2 out fp32 (router)
__device__ __half g_th[TT*DD];              // rms2 out fp16 (moe1 A)
__device__ __half g_midh[(size_t)MAXROWS*FF];  // moe1 out fp16
__device__ float  g_mid2[(size_t)MAXROWS*DD];  // moe2 out fp32
__device__ int    g_count[NE];
__device__ int    g_pair_e[TT*KTOP];
__device__ int    g_pair_pos[TT*KTOP];
__device__ float  g_pair_gate[TT*KTOP];
__device__ int    g_row_token[MAXROWS];
__device__ int    g_row_of_pair[TT*KTOP];

__device__ __forceinline__ float warp_sum(float v) {
    #pragma unroll
    for (int o = 16; o > 0; o >>= 1) v += __shfl_down_sync(0xffffffffu, v, o);
    return v;
}

__device__ __forceinline__ uint32_t smem_to_u32(const void* p) {
    uint32_t a;
    asm("{ .reg .u64 t; cvta.to.shared.u64 t, %1; cvt.u32.u64 %0, t; }"
        : "=r"(a) : "l"(p));
    return a;
}

__device__ __forceinline__ uint32_t pack2(float x, float y) {
    __half2 h = __floats2half2_rn(x, y);
    return *reinterpret_cast<uint32_t*>(&h);
}

__device__ __forceinline__ void cp_async16(uint32_t dst, const void* src) {
    asm volatile("cp.async.ca.shared.global [%0], [%1], 16;"
                 :: "r"(dst), "l"(src) : "memory");
}
#define CP_COMMIT() asm volatile("cp.async.commit_group;" ::: "memory")
#define CP_WAIT0()  asm volatile("cp.async.wait_group 0;" ::: "memory")

__device__ __forceinline__ void ldsm_x4(uint32_t* r, uint32_t addr) {
    asm volatile("ldmatrix.sync.aligned.m8n8.x4.shared.b16 {%0,%1,%2,%3}, [%4];"
        : "=r"(r[0]), "=r"(r[1]), "=r"(r[2]), "=r"(r[3]) : "r"(addr));
}
__device__ __forceinline__ void ldsm_x4_t(uint32_t* r, uint32_t addr) {
    asm volatile("ldmatrix.sync.aligned.m8n8.x4.trans.shared.b16 {%0,%1,%2,%3}, [%4];"
        : "=r"(r[0]), "=r"(r[1]), "=r"(r[2]), "=r"(r[3]) : "r"(addr));
}
__device__ __forceinline__ void mma16816(float* c, const uint32_t* a,
                                         uint32_t b0, uint32_t b1) {
    asm volatile(
        "mma.sync.aligned.m16n8k16.row.col.f32.f16.f16.f32 "
        "{%0,%1,%2,%3}, {%4,%5,%6,%7}, {%8,%9}, {%0,%1,%2,%3};"
        : "+f"(c[0]), "+f"(c[1]), "+f"(c[2]), "+f"(c[3])
        : "r"(a[0]), "r"(a[1]), "r"(a[2]), "r"(a[3]), "r"(b0), "r"(b1));
}

// ---------------- RMSNorm ----------------
template<bool OUT_F, bool OUT_H>
__device__ __forceinline__ void rms_core(const float* __restrict__ x,
                                         const float* __restrict__ w,
                                         float* __restrict__ outf,
                                         __half* __restrict__ outh) {
    int row = blockIdx.x;
    const float4* xr = (const float4*)(x + (size_t)row * DD);
    float4 vals[2];
    float ss = 0.f;
    #pragma unroll
    for (int l = 0; l < 2; l++) {
        float4 v = xr[threadIdx.x + l * 256];
        vals[l] = v;
        ss += v.x*v.x + v.y*v.y + v.z*v.z + v.w*v.w;
    }
    ss = warp_sum(ss);
    __shared__ float red[8];
    if ((threadIdx.x & 31) == 0) red[threadIdx.x >> 5] = ss;
    __syncthreads();
    float tot = 0.f;
    #pragma unroll
    for (int i = 0; i < 8; i++) tot += red[i];
    float inv = rsqrtf(tot / (float)DD + 1e-6f);
    const float4* wr = (const float4*)w;
    #pragma unroll
    for (int l = 0; l < 2; l++) {
        int idx = threadIdx.x + l * 256;
        float4 v = vals[l];
        float4 ww = wr[idx];
        float4 r;
        r.x = v.x * inv * ww.x; r.y = v.y * inv * ww.y;
        r.z = v.z * inv * ww.z; r.w = v.w * inv * ww.w;
        if (OUT_F) ((float4*)(outf + (size_t)row * DD))[idx] = r;
        if (OUT_H) {
            uint2 h; h.x = pack2(r.x, r.y); h.y = pack2(r.z, r.w);
            *(uint2*)(outh + (size_t)row * DD + idx * 4) = h;
        }
    }
}

__global__ void __launch_bounds__(256) k_rms1(const float* __restrict__ x,
                                              const float* __restrict__ w) {
    rms_core<false, true>(x, w, nullptr, g_hh);
}
// rms2 + MoE bookkeeping init folded in
__global__ void __launch_bounds__(256) k_rms2(const float* __restrict__ w) {
    rms_core<true, true>(g_x1, w, g_t, g_th);
    int gi = blockIdx.x * 256 + threadIdx.x;
    if (gi < NE) g_count[gi] = 0;
    if (gi < MAXROWS) g_row_token[gi] = 0;
}

// ---------------- fp16 HMMA GEMM ----------------
// A: fp16 global [M,K] staged via cp.async; B: fp32 global [K,N] cvt in staging.
// OUTMODE: 0 = fp32 C, 1 = fp16 C, 2 = RoPE epilogue -> fp16 [token][head][128].
#define TBM 128
#define TBN 256
#define BKH 32
#define ASZ 8192            // 128*32*2
#define BSZ 16384           // 32*256*2
#define TG_SMEM (2*ASZ + 2*BSZ)   // 49152
#define QKSTF 260
#define QKV_SMEM (128*QKSTF*4)    // 133120 (rope restage, reuses pipeline smem)

template<bool SILU, bool RESID, bool GATHER, int OUTMODE>
__device__ __forceinline__ void tgemm(
    const __half* __restrict__ A, const float* __restrict__ Bmat, void* __restrict__ Cv,
    int Kdim, int lda, int ldb, int ldc, int nt, int mt,
    const float* __restrict__ resid, const int* __restrict__ gather,
    __half* __restrict__ ropeout, int nheads, int headbase)
{
    extern __shared__ char smh[];
    const uint32_t smem_u = smem_to_u32(smh);
    const int tid = threadIdx.x;
    const int lane = tid & 31, warp = tid >> 5;
    const int wm = warp >> 2, wn = warp & 3;
    const int mlane = ((lane >> 3) & 1) * 8 + (lane & 7);
    const int lhi = lane >> 4;

    float acc[4][8][4];
    #pragma unroll
    for (int f = 0; f < 4; f++)
        #pragma unroll
        for (int nf = 0; nf < 8; nf++)
            #pragma unroll
            for (int i = 0; i < 4; i++) acc[f][nf][i] = 0.f;

    // A staging: 2 x 16B cp.async per thread
    const __half* aptr[2];
    uint32_t aoff[2];
    #pragma unroll
    for (int j = 0; j < 2; j++) {
        int id = tid + 256 * j;
        int row = id >> 2, qq = id & 3;
        int gr = mt * TBM + row;
        if (GATHER) gr = gather[gr];
        aptr[j] = A + (size_t)gr * lda + qq * 8;
        aoff[j] = ((row >> 1) << 7) + ((row & 1) << 6)
                + (((qq ^ ((row >> 1) & 3))) << 4);
    }
    // B staging: 8 float4/thread (fp32 weights, cvt to fp16)
    const float* bptr[8];
    uint32_t boff[8];
    #pragma unroll
    for (int j = 0; j < 8; j++) {
        int id = tid + 256 * j;
        int kr = id >> 6, nq = id & 63;
        bptr[j] = Bmat + (size_t)kr * ldb + nt * TBN + nq * 4;
        boff[j] = (kr << 9) + ((((nq >> 1) ^ (kr & 7))) << 4) + ((nq & 1) << 3);
    }

    float4 pb[8];
    // prologue: stage 0
    cp_async16(smem_u + aoff[0], aptr[0]);
    cp_async16(smem_u + aoff[1], aptr[1]);
    CP_COMMIT();
    #pragma unroll
    for (int j = 0; j < 8; j++) pb[j] = *(const float4*)(bptr[j]);
    {
        char* Bs = smh + 2 * ASZ;
        #pragma unroll
        for (int j = 0; j < 8; j++) {
            uint2 w; w.x = pack2(pb[j].x, pb[j].y); w.y = pack2(pb[j].z, pb[j].w);
            *(uint2*)(Bs + boff[j]) = w;
        }
    }
    CP_WAIT0();
    __syncthreads();

    const int nk = Kdim / BKH;
    for (int c = 0; c < nk; c++) {
        if (c + 1 < nk) {
            int ko = (c + 1) * BKH;
            uint32_t sbase = smem_u + ((c + 1) & 1) * ASZ;
            cp_async16(sbase + aoff[0], aptr[0] + ko);
            cp_async16(sbase + aoff[1], aptr[1] + ko);
            CP_COMMIT();
            #pragma unroll
            for (int j = 0; j < 8; j++) pb[j] = *(const float4*)(bptr[j] + (size_t)ko * ldb);
        }
        // compute current stage
        {
            const uint32_t Abase = smem_u + (c & 1) * ASZ;
            const uint32_t Bbase = smem_u + 2 * ASZ + (c & 1) * BSZ;
            #pragma unroll
            for (int s = 0; s < 2; s++) {
                uint32_t af[4][4];
                #pragma unroll
                for (int f = 0; f < 4; f++) {
                    int m = wm * 64 + f * 16 + mlane;
                    int ch = 2 * s + lhi;
                    ldsm_x4(af[f], Abase + ((m >> 1) << 7) + ((m & 1) << 6)
                                   + (((ch ^ ((m >> 1) & 3))) << 4));
                }
                uint32_t bf[4][4];
                #pragma unroll
                for (int g = 0; g < 4; g++) {
                    int kr = s * 16 + mlane;
                    int chn = wn * 8 + g * 2 + lhi;
                    ldsm_x4_t(bf[g], Bbase + (kr << 9) + (((chn ^ (kr & 7))) << 4));
                }
                #pragma unroll
                for (int f = 0; f < 4; f++)
                    #pragma unroll
                    for (int g = 0; g < 4; g++) {
                        mma16816(acc[f][g*2+0], af[f], bf[g][0], bf[g][1]);
                        mma16816(acc[f][g*2+1], af[f], bf[g][2], bf[g][3]);
                    }
            }
        }
        if (c + 1 < nk) {
            char* Bs = smh + 2 * ASZ + ((c + 1) & 1) * BSZ;
            #pragma unroll
            for (int j = 0; j < 8; j++) {
                uint2 w; w.x = pack2(pb[j].x, pb[j].y); w.y = pack2(pb[j].z, pb[j].w);
                *(uint2*)(Bs + boff[j]) = w;
            }
        }
        CP_WAIT0();
        __syncthreads();
    }

    const int r = lane >> 2, cl = lane & 3;
    if (OUTMODE == 2) {
        // RoPE epilogue: restage fp32 acc to smem, rotate, write fp16
        float* st = (float*)smh;
        #pragma unroll
        for (int f = 0; f < 4; f++)
            #pragma unroll
            for (int h = 0; h < 2; h++) {
                int row = wm * 64 + f * 16 + r + h * 8;
                #pragma unroll
                for (int nf = 0; nf < 8; nf++) {
                    int col = wn * 64 + nf * 8 + cl * 2;
                    float2 v; v.x = acc[f][nf][h*2]; v.y = acc[f][nf][h*2+1];
                    *(float2*)&st[row * QKSTF + col] = v;
                }
            }
        __syncthreads();
        int row = tid >> 1, h2 = tid & 1;
        int token = mt * TBM + row;
        int pos = token & (SS - 1);
        int head = headbase + h2;
        __half* dst = ropeout + ((size_t)token * nheads + head) * 128;
        const float* src = st + row * QKSTF + h2 * 128;
        #pragma unroll
        for (int dc = 0; dc < 8; dc++) {
            int d0 = dc * 8;
            float lo[8], hi[8];
            *(float4*)&lo[0] = *(const float4*)&src[d0];
            *(float4*)&lo[4] = *(const float4*)&src[d0 + 4];
            *(float4*)&hi[0] = *(const float4*)&src[64 + d0];
            *(float4*)&hi[4] = *(const float4*)&src[64 + d0 + 4];
            uint32_t olo[4], ohi[4];
            #pragma unroll
            for (int i = 0; i < 8; i += 2) {
                float ex0 = (float)(d0 + i) * (1.0f / 64.0f);
                float ex1 = (float)(d0 + i + 1) * (1.0f / 64.0f);
                float if0 = expf(-ex0 * 9.210340371976184f);
                float if1 = expf(-ex1 * 9.210340371976184f);
                float s0, c0, s1, c1;
                sincosf((float)pos * if0, &s0, &c0);
                sincosf((float)pos * if1, &s1, &c1);
                float a0 = lo[i]   * c0 - hi[i]   * s0;
                float b0 = lo[i]   * s0 + hi[i]   * c0;
                float a1 = lo[i+1] * c1 - hi[i+1] * s1;
                float b1 = lo[i+1] * s1 + hi[i+1] * c1;
                olo[i >> 1] = pack2(a0, a1);
                ohi[i >> 1] = pack2(b0, b1);
            }
            *(uint4*)(dst + d0)      = *(uint4*)olo;
            *(uint4*)(dst + 64 + d0) = *(uint4*)ohi;
        }
        return;
    }

    #pragma unroll
    for (int f = 0; f < 4; f++) {
        #pragma unroll
        for (int h = 0; h < 2; h++) {
            size_t gr = (size_t)(mt * TBM + wm * 64 + f * 16 + r + h * 8);
            const float* rrow = RESID ? (resid + gr * ldc) : nullptr;
            #pragma unroll
            for (int nf = 0; nf < 8; nf++) {
                int gc = nt * TBN + wn * 64 + nf * 8 + cl * 2;
                float v0 = acc[f][nf][h * 2 + 0];
                float v1 = acc[f][nf][h * 2 + 1];
                if (SILU) {
                    v0 = v0 / (1.f + __expf(-v0));
                    v1 = v1 / (1.f + __expf(-v1));
                }
                if (RESID) { v0 += rrow[gc]; v1 += rrow[gc + 1]; }
                if (OUTMODE == 1) {
                    __half2 o = __floats2half2_rn(v0, v1);
                    *(__half2*)((__half*)Cv + gr * ldc + gc) = o;
                } else {
                    float2 o; o.x = v0; o.y = v1;
                    *(float2*)((float*)Cv + gr * ldc + gc) = o;
                }
            }
        }
    }
}

// expert for a padded MoE tile, from g_count (8-iter prefix scan)
__device__ __forceinline__ int tile_expert(int ty) {
    int off = 0;
    for (int e = 0; e < NE; e++) {
        int pt = (g_count[e] + 127) >> 7;
        if (ty < off + pt) return e;
        off += pt;
    }
    return -1;
}

// fused QKV + RoPE: nt 0..7 -> Q (rope), 8..9 -> K (rope), 10..11 -> V (fp16)
__global__ void __launch_bounds__(256, 1) k_gemm_qkv(const float* __restrict__ Wq,
                                                     const float* __restrict__ Wk,
                                                     const float* __restrict__ Wv) {
    int nt = blockIdx.x, mt = blockIdx.y;
    if (nt < 8)
        tgemm<false,false,false,2>(g_hh, Wq, nullptr, DD, DD, HH*DKK, 0, nt, mt,
                                   nullptr, nullptr, g_qh, HH, nt * 2);
    else if (nt < 10)
        tgemm<false,false,false,2>(g_hh, Wk, nullptr, DD, DD, GG*DKK, 0, nt - 8, mt,
                                   nullptr, nullptr, g_kh, GG, (nt - 8) * 2);
    else
        tgemm<false,false,false,1>(g_hh, Wv, g_vh, DD, DD, GG*DVV, GG*DVV, nt - 10, mt,
                                   nullptr, nullptr, nullptr, 0, 0);
}
__global__ void __launch_bounds__(256, 1) k_gemm_o(const float* __restrict__ Wo,
                                                   const float* __restrict__ xin) {
    tgemm<false,true,false,0>(g_attnh, Wo, g_x1, HH*DVV, HH*DVV, DD, DD,
                              blockIdx.x, blockIdx.y, xin, nullptr, nullptr, 0, 0);
}
__global__ void __launch_bounds__(256, 1) k_moe1(const float* __restrict__ W1) {
    int e = tile_expert(blockIdx.y);
    if (e < 0) return;
    tgemm<true,false,true,1>(g_th, W1 + (long long)e * DD * FF, g_midh, DD, DD, FF, FF,
                             blockIdx.x, blockIdx.y, nullptr, g_row_token, nullptr, 0, 0);
}
__global__ void __launch_bounds__(256, 1) k_moe2(const float* __restrict__ W2) {
    int e = tile_expert(blockIdx.y);
    if (e < 0) return;
    tgemm<false,false,false,0>(g_midh, W2 + (long long)e * FF * DD, g_mid2,
                               FF, FF, DD, DD, blockIdx.x, blockIdx.y,
                               nullptr, nullptr, nullptr, 0, 0);
}

// ---------------- Flash attention, fp16 in/out (R8, known-good) ----------------
#define QROW 272
#define PLD 68
#define PSHROW 144
#define OFF_KS (64*QROW)
#define OFF_VS (2*64*QROW)
#define OFF_PS (3*64*QROW)
#define OFF_PSH (OFF_PS + 64*PLD*4)
#define OFF_MISC (OFF_PSH + 64*PSHROW)
#define ATTN_SMEM (OFF_MISC + 3*64*4)   // 79616

__global__ void __launch_bounds__(256) k_attn() {
    extern __shared__ char sma[];
    const uint32_t su = smem_to_u32(sma);
    float* ps   = (float*)(sma + OFF_PS);
    float* mrow = (float*)(sma + OFF_MISC);
    float* lrow = mrow + 64;
    float* arow = lrow + 64;
    const int qt = 15 - blockIdx.x;
    const int hh = blockIdx.y, b = blockIdx.z;
    const int g = hh >> 2;
    const int tid = threadIdx.x;
    const int lane = tid & 31, warp = tid >> 5;
    const int r = lane >> 2, cl = lane & 3;
    const int mlane = ((lane >> 3) & 1) * 8 + (lane & 7);
    const int lhi = lane >> 4;
    const int swm = warp >> 1, swn = warp & 1;
    const int m0 = swm * 16;

    for (int id = tid; id < 64 * 16; id += 256) {
        int m = id >> 4, c8 = (id & 15) << 3;
        const __half* src = g_qh + (((size_t)((b * SS + qt * 64 + m) * HH + hh)) << 7) + c8;
        *(uint4*)(sma + m * QROW + c8 * 2) = *(const uint4*)src;
    }
    if (tid < 64) { mrow[tid] = -1e30f; lrow[tid] = 0.f; }

    float oacc[8][4];
    #pragma unroll
    for (int nf = 0; nf < 8; nf++)
        #pragma unroll
        for (int i = 0; i < 4; i++) oacc[nf][i] = 0.f;

    const float scale = 0.08838834764831845f;

    for (int kt = 0; kt <= qt; kt++) {
        __syncthreads();
        for (int id = tid; id < 64 * 16; id += 256) {
            int n = id >> 4, c8 = (id & 15) << 3;
            size_t gidx = (((size_t)((b * SS + kt * 64 + n) * GG + g)) << 7) + c8;
            *(uint4*)(sma + OFF_KS + n * QROW + c8 * 2) = *(const uint4*)(g_kh + gidx);
            *(uint4*)(sma + OFF_VS + n * QROW + c8 * 2) = *(const uint4*)(g_vh + gidx);
        }
        __syncthreads();

        float sacc[4][4];
        #pragma unroll
        for (int t = 0; t < 4; t++)
            #pragma unroll
            for (int i = 0; i < 4; i++) sacc[t][i] = 0.f;
        const int sn0 = swn * 32;
        const uint32_t qb = su + (m0 + mlane) * QROW + lhi * 16;
        const uint32_t kb0 = su + OFF_KS + (sn0 + mlane) * QROW + lhi * 16;
        const uint32_t kb1 = kb0 + 16 * QROW;
        #pragma unroll
        for (int kc = 0; kc < 8; kc++) {
            uint32_t af[4], bk0[4], bk1[4];
            ldsm_x4(af, qb + kc * 32);
            ldsm_x4(bk0, kb0 + kc * 32);
            ldsm_x4(bk1, kb1 + kc * 32);
            mma16816(sacc[0], af, bk0[0], bk0[2]);
            mma16816(sacc[1], af, bk0[1], bk0[3]);
            mma16816(sacc[2], af, bk1[0], bk1[2]);
            mma16816(sacc[3], af, bk1[1], bk1[3]);
        }
        {
            int gm0 = qt * 64 + m0 + r;
            #pragma unroll
            for (int t = 0; t < 4; t++) {
                int gn = kt * 64 + sn0 + t * 8 + 2 * cl;
                float v0 = sacc[t][0] * scale; if (gn     > gm0)     v0 = -1e30f;
                float v1 = sacc[t][1] * scale; if (gn + 1 > gm0)     v1 = -1e30f;
                float v2 = sacc[t][2] * scale; if (gn     > gm0 + 8) v2 = -1e30f;
                float v3 = sacc[t][3] * scale; if (gn + 1 > gm0 + 8) v3 = -1e30f;
                float2 p01; p01.x = v0; p01.y = v1;
                float2 p23; p23.x = v2; p23.y = v3;
                *(float2*)&ps[(m0 + r) * PLD + sn0 + t * 8 + 2 * cl] = p01;
                *(float2*)&ps[(m0 + r + 8) * PLD + sn0 + t * 8 + 2 * cl] = p23;
            }
        }
        __syncthreads();
        {
            int row = tid >> 2, part = tid & 3;
            float mx = mrow[row];
            const float* pr = ps + row * PLD + part * 16;
            float tmax = -1e30f;
            #pragma unroll
            for (int n = 0; n < 16; n++) tmax = fmaxf(tmax, pr[n]);
            tmax = fmaxf(tmax, __shfl_xor_sync(0xffffffffu, tmax, 1));
            tmax = fmaxf(tmax, __shfl_xor_sync(0xffffffffu, tmax, 2));
            float nm = fmaxf(mx, tmax);
            float al = __expf(mx - nm);
            float sum = 0.f;
            __half* ph = (__half*)(sma + OFF_PSH + row * PSHROW) + part * 16;
            #pragma unroll
            for (int n = 0; n < 16; n += 2) {
                float p0 = __expf(pr[n] - nm);
                float p1 = __expf(pr[n + 1] - nm);
                sum += p0 + p1;
                *(__half2*)(ph + n) = __floats2half2_rn(p0, p1);
            }
            sum += __shfl_xor_sync(0xffffffffu, sum, 1);
            sum += __shfl_xor_sync(0xffffffffu, sum, 2);
            if (part == 0) {
                lrow[row] = lrow[row] * al + sum;
                mrow[row] = nm;
                arow[row] = al;
            }
        }
        __syncthreads();
        {
            float al0 = arow[m0 + r], al1 = arow[m0 + r + 8];
            #pragma unroll
            for (int nf = 0; nf < 8; nf++) {
                oacc[nf][0] *= al0; oacc[nf][1] *= al0;
                oacc[nf][2] *= al1; oacc[nf][3] *= al1;
            }
            const int dn0 = swn * 64;
            const uint32_t pb = su + OFF_PSH + (m0 + mlane) * PSHROW + lhi * 16;
            const uint32_t vb = su + OFF_VS + mlane * QROW + dn0 * 2 + lhi * 16;
            #pragma unroll
            for (int kc = 0; kc < 4; kc++) {
                uint32_t af[4];
                ldsm_x4(af, pb + kc * 32);
                #pragma unroll
                for (int g2 = 0; g2 < 4; g2++) {
                    uint32_t bf[4];
                    ldsm_x4_t(bf, vb + kc * 16 * QROW + g2 * 32);
                    mma16816(oacc[g2*2+0], af, bf[0], bf[1]);
                    mma16816(oacc[g2*2+1], af, bf[2], bf[3]);
                }
            }
        }
    }
    {
        float inv0 = 1.f / lrow[m0 + r];
        float inv1 = 1.f / lrow[m0 + r + 8];
        const int dn0 = swn * 64;
        __half* dst0 = g_attnh + (((size_t)((b * SS + qt * 64 + m0 + r) * HH + hh)) << 7);
        __half* dst1 = g_attnh + (((size_t)((b * SS + qt * 64 + m0 + r + 8) * HH + hh)) << 7);
        #pragma unroll
        for (int nf = 0; nf < 8; nf++) {
            int d = dn0 + nf * 8 + 2 * cl;
            *(__half2*)(dst0 + d) = __floats2half2_rn(oacc[nf][0] * inv0, oacc[nf][1] * inv0);
            *(__half2*)(dst1 + d) = __floats2half2_rn(oacc[nf][2] * inv1, oacc[nf][3] * inv1);
        }
    }
}

// ---------------- router + MoE bookkeeping ----------------
__global__ void __launch_bounds__(128) k_router(const float* __restrict__ Wr) {
    int tok = blockIdx.x;
    const float* tr = g_t + (size_t)tok * DD;
    float acc[8] = {0,0,0,0,0,0,0,0};
    for (int d = threadIdx.x; d < DD; d += 128) {
        float tv = tr[d];
        const float4* wr = (const float4*)(Wr + (size_t)d * 8);
        float4 w0 = wr[0], w1 = wr[1];
        acc[0] = fmaf(tv, w0.x, acc[0]); acc[1] = fmaf(tv, w0.y, acc[1]);
        acc[2] = fmaf(tv, w0.z, acc[2]); acc[3] = fmaf(tv, w0.w, acc[3]);
        acc[4] = fmaf(tv, w1.x, acc[4]); acc[5] = fmaf(tv, w1.y, acc[5]);
        acc[6] = fmaf(tv, w1.z, acc[6]); acc[7] = fmaf(tv, w1.w, acc[7]);
    }
    __shared__ float red[4][8];
    #pragma unroll
    for (int e = 0; e < 8; e++) {
        float v = warp_sum(acc[e]);
        if ((threadIdx.x & 31) == 0) red[threadIdx.x >> 5][e] = v;
    }
    __syncthreads();
    if (threadIdx.x == 0) {
        float lg[8];
        #pragma unroll
        for (int e = 0; e < 8; e++) lg[e] = red[0][e] + red[1][e] + red[2][e] + red[3][e];
        int i0 = 0;
        for (int e = 1; e < 8; e++) if (lg[e] > lg[i0]) i0 = e;
        int i1 = -1;
        for (int e = 0; e < 8; e++) {
            if (e == i0) continue;
            if (i1 < 0 || lg[e] > lg[i1]) i1 = e;
        }
        float e1v = __expf(lg[i1] - lg[i0]);
        float s = 1.f + e1v;
        float gg0 = 1.f / s, gg1 = e1v / s;
        int p0 = atomicAdd(&g_count[i0], 1);
        int p1 = atomicAdd(&g_count[i1], 1);
        g_pair_e[tok*2]   = i0; g_pair_pos[tok*2]   = p0; g_pair_gate[tok*2]   = gg0;
        g_pair_e[tok*2+1] = i1; g_pair_pos[tok*2+1] = p1; g_pair_gate[tok*2+1] = gg1;
    }
}

// row placement: padded-prefix offsets computed inline from g_count
__global__ void k_rows_place() {
    int p = blockIdx.x * 256 + threadIdx.x;
    if (p >= TT * KTOP) return;
    int e = g_pair_e[p];
    int off = 0;
    for (int q = 0; q < NE; q++) {
        int pt = (g_count[q] + 127) >> 7;
        if (q < e) off += pt << 7;
    }
    int row = off + g_pair_pos[p];
    g_row_token[row] = p >> 1;
    g_row_of_pair[p] = row;
}

__global__ void __launch_bounds__(256) k_combine(float* __restrict__ out) {
    int tok = blockIdx.x;
    int r0 = g_row_of_pair[tok*2], r1 = g_row_of_pair[tok*2+1];
    float gg0 = g_pair_gate[tok*2], gg1 = g_pair_gate[tok*2+1];
    const float4* a  = (const float4*)(g_x1  + (size_t)tok * DD);
    const float4* m0 = (const float4*)(g_mid2 + (size_t)r0 * DD);
    const float4* m1 = (const float4*)(g_mid2 + (size_t)r1 * DD);
    float4* o4 = (float4*)(out + (size_t)tok * DD);
    for (int i = threadIdx.x; i < DD / 4; i += 256) {
        float4 av = a[i], v0 = m0[i], v1 = m1[i], r;
        r.x = av.x + gg0 * v0.x + gg1 * v1.x;
        r.y = av.y + gg0 * v0.y + gg1 * v1.y;
        r.z = av.z + gg0 * v0.z + gg1 * v1.z;
        r.w = av.w + gg0 * v0.w + gg1 * v1.w;
        o4[i] = r;
    }
}

// ---------------- launch ----------------
extern "C" void kernel_launch(void* const* d_in, const int* in_sizes, int n_in,
                              void* d_out, int out_size) {
    const float* x    = (const float*)d_in[0];
    const float* ln1w = (const float*)d_in[1];
    const float* Wq   = (const float*)d_in[2];
    const float* Wk   = (const float*)d_in[3];
    const float* Wv   = (const float*)d_in[4];
    const float* Wo   = (const float*)d_in[5];
    const float* ln2w = (const float*)d_in[6];
    const float* Wr   = (const float*)d_in[7];
    const float* W1   = (const float*)d_in[8];
    const float* W2   = (const float*)d_in[9];
    float* out = (float*)d_out;
    (void)in_sizes; (void)n_in; (void)out_size;

    cudaFuncSetAttribute(k_gemm_qkv, cudaFuncAttributeMaxDynamicSharedMemorySize, QKV_SMEM);
    cudaFuncSetAttribute(k_gemm_o,   cudaFuncAttributeMaxDynamicSharedMemorySize, TG_SMEM);
    cudaFuncSetAttribute(k_moe1,     cudaFuncAttributeMaxDynamicSharedMemorySize, TG_SMEM);
    cudaFuncSetAttribute(k_moe2,     cudaFuncAttributeMaxDynamicSharedMemorySize, TG_SMEM);
    cudaFuncSetAttribute(k_attn,     cudaFuncAttributeMaxDynamicSharedMemorySize, ATTN_SMEM);

    k_rms1<<<TT, 256>>>(x, ln1w);
    k_gemm_qkv<<<dim3(12, TT/TBM), 256, QKV_SMEM>>>(Wq, Wk, Wv);  // 192 CTAs, rope fused
    k_attn<<<dim3(16, 16, 2), 256, ATTN_SMEM>>>();
    k_gemm_o<<<dim3(DD/TBN, TT/TBM), 256, TG_SMEM>>>(Wo, x);      // 128 CTAs
    k_rms2<<<TT, 256>>>(ln2w);                                    // + bookkeeping init
    k_router<<<TT, 128>>>(Wr);
    k_rows_place<<<(TT * KTOP + 255) / 256, 256>>>();
    k_moe1<<<dim3(FF/TBN, MAXTILES), 256, TG_SMEM>>>(W1);         // (16,40)
    k_moe2<<<dim3(DD/TBN, MAXTILES), 256, TG_SMEM>>>(W2);         // (8,40)
    k_combine<<<TT, 256>>>(out);
}